// round 5
// baseline (speedup 1.0000x reference)
#include <cuda_runtime.h>
#include <cstddef>

#define N_NODES   100000
#define N_EDGES   1600000
#define IN_DIM    256
#define HIDDEN    128
#define N_CLASSES 40

#define SCAN_B 1024
#define NBLK   ((N_NODES + SCAN_B - 1) / SCAN_B)   // 98

// ---------------- static device scratch (no allocations allowed) ----------------
__device__ __align__(16) float g_dinv[N_NODES];
__device__ int  g_cnt[N_NODES];
__device__ int  g_rowptr[N_NODES + 1];
__device__ int  g_cursor[N_NODES];
__device__ int  g_bsum[NBLK];
__device__ int  g_cidx[N_EDGES];
__device__ __align__(16) float g_P1[(size_t)N_NODES * HIDDEN];
__device__ __align__(16) float g_X1[(size_t)N_NODES * HIDDEN];
__device__ __align__(16) float g_P2[(size_t)N_NODES * N_CLASSES];

// ---------------- CSR build ----------------
__global__ void zero_cnt_kernel() {
    int i = blockIdx.x * blockDim.x + threadIdx.x;
    if (i < N_NODES) g_cnt[i] = 0;
}

// edge_index is INT32 on device (JAX x64 disabled downcasts int64 -> int32).
__global__ void hist_kernel(const int* __restrict__ ei) {
    int e = blockIdx.x * blockDim.x + threadIdx.x;
    if (e < N_EDGES) atomicAdd(&g_cnt[ei[N_EDGES + e]], 1);
}

// per-block exclusive scan of g_cnt -> g_rowptr (pre-offset), block totals -> g_bsum
__global__ void scan1_kernel() {
    __shared__ int sh[SCAN_B];
    int tid = threadIdx.x;
    int i = blockIdx.x * SCAN_B + tid;
    int v = (i < N_NODES) ? g_cnt[i] : 0;
    sh[tid] = v;
    __syncthreads();
#pragma unroll
    for (int off = 1; off < SCAN_B; off <<= 1) {
        int t = (tid >= off) ? sh[tid - off] : 0;
        __syncthreads();
        sh[tid] += t;
        __syncthreads();
    }
    if (i < N_NODES) g_rowptr[i] = sh[tid] - v;   // exclusive
    if (tid == SCAN_B - 1) g_bsum[blockIdx.x] = sh[tid];
}

// serial scan of NBLK (=98) block sums (tiny)
__global__ void scan2_kernel() {
    if (threadIdx.x == 0) {
        int acc = 0;
        for (int b = 0; b < NBLK; b++) {
            int v = g_bsum[b];
            g_bsum[b] = acc;
            acc += v;
        }
    }
}

// add block offsets; init cursor; compute dinv; set rowptr[N]
__global__ void scan3_kernel() {
    int i = blockIdx.x * blockDim.x + threadIdx.x;
    if (i < N_NODES) {
        int r = g_rowptr[i] + g_bsum[i / SCAN_B];
        g_rowptr[i] = r;
        g_cursor[i] = r;
        g_dinv[i] = rsqrtf((float)g_cnt[i] + 1.0f);   // +1 self-loop
    }
    if (i == 0) g_rowptr[N_NODES] = N_EDGES;
}

__global__ void place_kernel(const int* __restrict__ ei) {
    int e = blockIdx.x * blockDim.x + threadIdx.x;
    if (e < N_EDGES) {
        int s = ei[e];
        int d = ei[N_EDGES + e];
        int pos = atomicAdd(&g_cursor[d], 1);
        g_cidx[pos] = s;
    }
}

// ---------------- tiled SGEMM, row-scale epilogue: P = dinv[row] * (A @ B) ----------------
template <int BM, int BN, int BK, int TM, int TN>
__global__ void gemm_scaled_kernel(const float* __restrict__ A,
                                   const float* __restrict__ B,
                                   float* __restrict__ P,
                                   int M, int N, int K) {
    constexpr int NT = (BM / TM) * (BN / TN);
    __shared__ float As[BK][BM + 4];
    __shared__ float Bs[BK][BN];

    const int tid  = threadIdx.x;
    const int tCol = tid % (BN / TN);
    const int tRow = tid / (BN / TN);
    const int rowBase = blockIdx.x * BM;

    float acc[TM][TN];
#pragma unroll
    for (int i = 0; i < TM; i++)
#pragma unroll
        for (int j = 0; j < TN; j++) acc[i][j] = 0.0f;

    for (int k0 = 0; k0 < K; k0 += BK) {
#pragma unroll
        for (int i = tid; i < BM * BK / 4; i += NT) {
            int r  = i / (BK / 4);
            int cc = (i % (BK / 4)) * 4;
            int gr = rowBase + r;
            float4 v = make_float4(0.f, 0.f, 0.f, 0.f);
            if (gr < M)
                v = *reinterpret_cast<const float4*>(A + (size_t)gr * K + k0 + cc);
            As[cc + 0][r] = v.x;
            As[cc + 1][r] = v.y;
            As[cc + 2][r] = v.z;
            As[cc + 3][r] = v.w;
        }
#pragma unroll
        for (int i = tid; i < BK * BN / 4; i += NT) {
            int r  = i / (BN / 4);
            int cc = (i % (BN / 4)) * 4;
            float4 v = make_float4(0.f, 0.f, 0.f, 0.f);
            if (cc + 3 < N) {
                v = *reinterpret_cast<const float4*>(B + (size_t)(k0 + r) * N + cc);
            } else {
                if (cc + 0 < N) v.x = B[(size_t)(k0 + r) * N + cc + 0];
                if (cc + 1 < N) v.y = B[(size_t)(k0 + r) * N + cc + 1];
                if (cc + 2 < N) v.z = B[(size_t)(k0 + r) * N + cc + 2];
            }
            Bs[r][cc + 0] = v.x;
            Bs[r][cc + 1] = v.y;
            Bs[r][cc + 2] = v.z;
            Bs[r][cc + 3] = v.w;
        }
        __syncthreads();

#pragma unroll
        for (int k = 0; k < BK; k++) {
            float rm[TM], rn[TN];
#pragma unroll
            for (int i = 0; i < TM; i++) rm[i] = As[k][tRow * TM + i];
#pragma unroll
            for (int j = 0; j < TN; j++) rn[j] = Bs[k][tCol * TN + j];
#pragma unroll
            for (int i = 0; i < TM; i++)
#pragma unroll
                for (int j = 0; j < TN; j++) acc[i][j] += rm[i] * rn[j];
        }
        __syncthreads();
    }

#pragma unroll
    for (int i = 0; i < TM; i++) {
        int row = rowBase + tRow * TM + i;
        if (row >= M) continue;
        float s = g_dinv[row];
#pragma unroll
        for (int j = 0; j < TN; j++) {
            int col = tCol * TN + j;
            if (col < N)
                P[(size_t)row * N + col] = acc[i][j] * s;
        }
    }
}

// ---------------- layer-1 aggregation: warp per node over 128 cols ----------------
// X1[n] = relu( dinv[n] * (P1[n] + sum_{s in nbrs(n)} P1[s]) + b1 )
__global__ void agg1_kernel(const float* __restrict__ b1) {
    int t = blockIdx.x * blockDim.x + threadIdx.x;
    int n = t >> 5;
    int c = t & 31;            // float4 chunk (4 cols)
    if (n >= N_NODES) return;

    int beg = g_rowptr[n];
    int end = g_rowptr[n + 1];
    float4 acc = *reinterpret_cast<const float4*>(g_P1 + (size_t)n * HIDDEN + c * 4);
    for (int e = beg; e < end; e++) {
        int s = g_cidx[e];     // broadcast across warp
        float4 v = *reinterpret_cast<const float4*>(g_P1 + (size_t)s * HIDDEN + c * 4);
        acc.x += v.x; acc.y += v.y; acc.z += v.z; acc.w += v.w;
    }
    float sc = g_dinv[n];
    float4 bb = *reinterpret_cast<const float4*>(b1 + c * 4);
    float4 o;
    o.x = fmaxf(fmaf(acc.x, sc, bb.x), 0.0f);
    o.y = fmaxf(fmaf(acc.y, sc, bb.y), 0.0f);
    o.z = fmaxf(fmaf(acc.z, sc, bb.z), 0.0f);
    o.w = fmaxf(fmaf(acc.w, sc, bb.w), 0.0f);
    *reinterpret_cast<float4*>(g_X1 + (size_t)n * HIDDEN + c * 4) = o;
}

// ---------------- layer-2 aggregation: 10 float4 chunks per node (40 cols) ----------------
__global__ void agg2_kernel(const float* __restrict__ b2, float* __restrict__ out) {
    int t = blockIdx.x * blockDim.x + threadIdx.x;
    int n = t / 10;
    int c = t % 10;
    if (n >= N_NODES) return;

    int beg = g_rowptr[n];
    int end = g_rowptr[n + 1];
    float4 acc = *reinterpret_cast<const float4*>(g_P2 + (size_t)n * N_CLASSES + c * 4);
    for (int e = beg; e < end; e++) {
        int s = g_cidx[e];
        float4 v = *reinterpret_cast<const float4*>(g_P2 + (size_t)s * N_CLASSES + c * 4);
        acc.x += v.x; acc.y += v.y; acc.z += v.z; acc.w += v.w;
    }
    float sc = g_dinv[n];
    float4 bb = *reinterpret_cast<const float4*>(b2 + c * 4);
    float4 o;
    o.x = fmaf(acc.x, sc, bb.x);
    o.y = fmaf(acc.y, sc, bb.y);
    o.z = fmaf(acc.z, sc, bb.z);
    o.w = fmaf(acc.w, sc, bb.w);
    *reinterpret_cast<float4*>(out + (size_t)n * N_CLASSES + c * 4) = o;
}

// ---------------- launch ----------------
extern "C" void kernel_launch(void* const* d_in, const int* in_sizes, int n_in,
                              void* d_out, int out_size) {
    const float* x  = (const float*)d_in[0];
    const int*   ei = (const int*)d_in[1];     // int32! (JAX x64 disabled)
    const float* W1 = (const float*)d_in[2];
    const float* b1 = (const float*)d_in[3];
    const float* W2 = (const float*)d_in[4];
    const float* b2 = (const float*)d_in[5];
    float* out = (float*)d_out;

    float *p1, *x1, *p2;
    cudaGetSymbolAddress((void**)&p1, g_P1);
    cudaGetSymbolAddress((void**)&x1, g_X1);
    cudaGetSymbolAddress((void**)&p2, g_P2);

    const int T = 256;

    // CSR build + dinv
    zero_cnt_kernel<<<(N_NODES + T - 1) / T, T>>>();
    hist_kernel<<<(N_EDGES + T - 1) / T, T>>>(ei);
    scan1_kernel<<<NBLK, SCAN_B>>>();
    scan2_kernel<<<1, 32>>>();
    scan3_kernel<<<(N_NODES + T - 1) / T, T>>>();
    place_kernel<<<(N_EDGES + T - 1) / T, T>>>(ei);

    // layer 1
    gemm_scaled_kernel<128, 128, 16, 8, 8>
        <<<(N_NODES + 127) / 128, 256>>>(x, W1, p1, N_NODES, HIDDEN, IN_DIM);
    agg1_kernel<<<(N_NODES * 32 + T - 1) / T, T>>>(b1);

    // layer 2
    gemm_scaled_kernel<128, 64, 16, 8, 8>
        <<<(N_NODES + 127) / 128, 128>>>(x1, W2, p2, N_NODES, N_CLASSES, HIDDEN);
    agg2_kernel<<<(N_NODES * 10 + T - 1) / T, T>>>(b2, out);
}

// round 7
// speedup vs baseline: 1.4123x; 1.4123x over previous
#include <cuda_runtime.h>
#include <cuda_bf16.h>
#include <cstdint>
#include <cstddef>

#define N_NODES   100000
#define N_EDGES   1600000
#define IN_DIM    256
#define HIDDEN    128
#define N_CLASSES 40

#define SCAN_B 1024
#define NBLK   ((N_NODES + SCAN_B - 1) / SCAN_B)   // 98

// ---------------- static device scratch (no allocations allowed) ----------------
__device__ __align__(16) float g_dinv[N_NODES];
__device__ int  g_cnt[N_NODES];
__device__ int  g_rowptr[N_NODES + 1];
__device__ int  g_cursor[N_NODES];
__device__ int  g_bsum[NBLK];
__device__ int  g_cidx[N_EDGES];
__device__ __align__(16) float g_P1[(size_t)N_NODES * HIDDEN];
__device__ __align__(16) float g_X1[(size_t)N_NODES * HIDDEN];
__device__ __align__(16) float g_P2[(size_t)N_NODES * N_CLASSES];
// W1 split into bf16 hi/lo, TRANSPOSED to [n][k] (n=HIDDEN rows, k=IN_DIM cols)
__device__ __align__(16) __nv_bfloat16 g_Wth[HIDDEN * IN_DIM];
__device__ __align__(16) __nv_bfloat16 g_Wtl[HIDDEN * IN_DIM];

// ---------------- CSR build ----------------
__global__ void zero_cnt_kernel() {
    int i = blockIdx.x * blockDim.x + threadIdx.x;
    if (i < N_NODES) g_cnt[i] = 0;
}

__global__ void hist_kernel(const int* __restrict__ ei) {
    int e = blockIdx.x * blockDim.x + threadIdx.x;
    if (e < N_EDGES) atomicAdd(&g_cnt[ei[N_EDGES + e]], 1);
}

__global__ void scan1_kernel() {
    __shared__ int sh[SCAN_B];
    int tid = threadIdx.x;
    int i = blockIdx.x * SCAN_B + tid;
    int v = (i < N_NODES) ? g_cnt[i] : 0;
    sh[tid] = v;
    __syncthreads();
#pragma unroll
    for (int off = 1; off < SCAN_B; off <<= 1) {
        int t = (tid >= off) ? sh[tid - off] : 0;
        __syncthreads();
        sh[tid] += t;
        __syncthreads();
    }
    if (i < N_NODES) g_rowptr[i] = sh[tid] - v;
    if (tid == SCAN_B - 1) g_bsum[blockIdx.x] = sh[tid];
}

__global__ void scan2_kernel() {
    if (threadIdx.x == 0) {
        int acc = 0;
        for (int b = 0; b < NBLK; b++) {
            int v = g_bsum[b];
            g_bsum[b] = acc;
            acc += v;
        }
    }
}

__global__ void scan3_kernel() {
    int i = blockIdx.x * blockDim.x + threadIdx.x;
    if (i < N_NODES) {
        int r = g_rowptr[i] + g_bsum[i / SCAN_B];
        g_rowptr[i] = r;
        g_cursor[i] = r;
        g_dinv[i] = rsqrtf((float)g_cnt[i] + 1.0f);
    }
    if (i == 0) g_rowptr[N_NODES] = N_EDGES;
}

__global__ void place_kernel(const int* __restrict__ ei) {
    int e = blockIdx.x * blockDim.x + threadIdx.x;
    if (e < N_EDGES) {
        int s = ei[e];
        int d = ei[N_EDGES + e];
        int pos = atomicAdd(&g_cursor[d], 1);
        g_cidx[pos] = s;
    }
}

// ---------------- W1 split + transpose (once per launch, tiny) ----------------
__global__ void wsplit_kernel(const float* __restrict__ W1) {
    int i = blockIdx.x * blockDim.x + threadIdx.x;   // over HIDDEN*IN_DIM, n-major
    if (i >= HIDDEN * IN_DIM) return;
    int n = i / IN_DIM;
    int k = i % IN_DIM;
    float f = W1[(size_t)k * HIDDEN + n];
    __nv_bfloat16 h = __float2bfloat16(f);
    __nv_bfloat16 l = __float2bfloat16(f - __bfloat162float(h));
    g_Wth[i] = h;
    g_Wtl[i] = l;
}

// ================= warp-MMA split-bf16 GEMM for layer 1 =================
// P1[m][n] = dinv[m]*sum_k x[m][k]*W1[k][n] via xh@wh + xh@wl + xl@wh.
// mma.sync.aligned.m16n8k16 bf16 — standard PTX, legal on plain sm_103 target.
#define PITCH 40   // bf16 elements per smem row (32 data + 8 pad); 80B, 16B-aligned

__device__ __forceinline__ uint32_t pack_bf16_hi(float f0, float f1) {
    uint32_t r;
    asm("cvt.rn.bf16x2.f32 %0, %1, %2;" : "=r"(r) : "f"(f1), "f"(f0));  // low=f0, high=f1
    return r;
}

__device__ __forceinline__ void mma_bf16(float c[4], uint32_t a0, uint32_t a1, uint32_t a2,
                                         uint32_t a3, uint32_t b0, uint32_t b1) {
    asm volatile(
        "mma.sync.aligned.m16n8k16.row.col.f32.bf16.bf16.f32 "
        "{%0,%1,%2,%3}, {%4,%5,%6,%7}, {%8,%9}, {%0,%1,%2,%3};"
        : "+f"(c[0]), "+f"(c[1]), "+f"(c[2]), "+f"(c[3])
        : "r"(a0), "r"(a1), "r"(a2), "r"(a3), "r"(b0), "r"(b1));
}

__global__ void __launch_bounds__(256, 1) gemm1_mma_kernel(const float* __restrict__ X,
                                                           float* __restrict__ P) {
    __shared__ __align__(16) __nv_bfloat16 As_h[128 * PITCH];
    __shared__ __align__(16) __nv_bfloat16 As_l[128 * PITCH];
    __shared__ __align__(16) __nv_bfloat16 Bs_h[128 * PITCH];
    __shared__ __align__(16) __nv_bfloat16 Bs_l[128 * PITCH];

    const int tid = threadIdx.x, lane = tid & 31, wid = tid >> 5;
    const int warpM = wid & 3;      // 4 warps over M (32 rows each)
    const int warpN = wid >> 2;     // 2 warps over N (64 cols each)
    const int rowBase = blockIdx.x * 128;
    const int gq = lane >> 2;       // groupID 0..7
    const int tg = lane & 3;        // thread-in-group 0..3

    float acc[2][8][4];
#pragma unroll
    for (int m = 0; m < 2; m++)
#pragma unroll
        for (int n = 0; n < 8; n++)
#pragma unroll
            for (int r = 0; r < 4; r++) acc[m][n][r] = 0.0f;

    for (int k0 = 0; k0 < IN_DIM; k0 += 32) {
        // ---- stage A: 128 rows x 32 k fp32 -> split bf16 hi/lo ----
#pragma unroll
        for (int i = tid; i < 1024; i += 256) {       // 1024 float4
            int r  = i >> 3;
            int c4 = (i & 7) * 4;
            int gr = rowBase + r;
            float4 v = (gr < N_NODES)
                ? *reinterpret_cast<const float4*>(X + (size_t)gr * IN_DIM + k0 + c4)
                : make_float4(0.f, 0.f, 0.f, 0.f);
            float h0 = __bfloat162float(__float2bfloat16(v.x));
            float h1 = __bfloat162float(__float2bfloat16(v.y));
            float h2 = __bfloat162float(__float2bfloat16(v.z));
            float h3 = __bfloat162float(__float2bfloat16(v.w));
            uint32_t* ph = reinterpret_cast<uint32_t*>(As_h + r * PITCH + c4);
            uint32_t* pl = reinterpret_cast<uint32_t*>(As_l + r * PITCH + c4);
            ph[0] = pack_bf16_hi(h0, h1);
            ph[1] = pack_bf16_hi(h2, h3);
            pl[0] = pack_bf16_hi(v.x - h0, v.y - h1);
            pl[1] = pack_bf16_hi(v.z - h2, v.w - h3);
        }
        // ---- stage B: copy Wt chunk [128 n][32 k] bf16 hi/lo (pure uint4 copy) ----
#pragma unroll
        for (int i = tid; i < 1024; i += 256) {       // 2 halves x 512 uint4
            int half = i >> 9;
            int j = i & 511;
            int n = j >> 2;
            int q = (j & 3) * 8;                       // 8 bf16 per uint4
            const __nv_bfloat16* src = (half ? g_Wtl : g_Wth) + (size_t)n * IN_DIM + k0 + q;
            __nv_bfloat16* dst = (half ? Bs_l : Bs_h) + n * PITCH + q;
            *reinterpret_cast<uint4*>(dst) = *reinterpret_cast<const uint4*>(src);
        }
        __syncthreads();

#pragma unroll
        for (int kk = 0; kk < 32; kk += 16) {
            // B fragments for this warp's 8 n-tiles
            uint32_t bh[8][2], bl[8][2];
#pragma unroll
            for (int nt = 0; nt < 8; nt++) {
                int n = warpN * 64 + nt * 8 + gq;
                int kc = kk + tg * 2;
                const uint32_t* bhp = reinterpret_cast<const uint32_t*>(Bs_h + n * PITCH + kc);
                const uint32_t* blp = reinterpret_cast<const uint32_t*>(Bs_l + n * PITCH + kc);
                bh[nt][0] = bhp[0]; bh[nt][1] = bhp[4];   // +8 bf16 = +4 u32
                bl[nt][0] = blp[0]; bl[nt][1] = blp[4];
            }
#pragma unroll
            for (int mt = 0; mt < 2; mt++) {
                int r0 = warpM * 32 + mt * 16 + gq;
                int kc = kk + tg * 2;
                const uint32_t* ah0 = reinterpret_cast<const uint32_t*>(As_h + r0 * PITCH + kc);
                const uint32_t* ah8 = reinterpret_cast<const uint32_t*>(As_h + (r0 + 8) * PITCH + kc);
                const uint32_t* al0 = reinterpret_cast<const uint32_t*>(As_l + r0 * PITCH + kc);
                const uint32_t* al8 = reinterpret_cast<const uint32_t*>(As_l + (r0 + 8) * PITCH + kc);
                uint32_t a0 = ah0[0], a1 = ah8[0], a2 = ah0[4], a3 = ah8[4];
                uint32_t l0 = al0[0], l1 = al8[0], l2 = al0[4], l3 = al8[4];
#pragma unroll
                for (int nt = 0; nt < 8; nt++) {
                    mma_bf16(acc[mt][nt], a0, a1, a2, a3, bh[nt][0], bh[nt][1]);   // hh
                    mma_bf16(acc[mt][nt], a0, a1, a2, a3, bl[nt][0], bl[nt][1]);   // hl
                    mma_bf16(acc[mt][nt], l0, l1, l2, l3, bh[nt][0], bh[nt][1]);   // lh
                }
            }
        }
        __syncthreads();
    }

    // ---- epilogue: scale by dinv[row], write P1 ----
#pragma unroll
    for (int mt = 0; mt < 2; mt++) {
        int r0 = rowBase + warpM * 32 + mt * 16 + gq;
        int r1 = r0 + 8;
        float d0 = (r0 < N_NODES) ? g_dinv[r0] : 0.f;
        float d1 = (r1 < N_NODES) ? g_dinv[r1] : 0.f;
#pragma unroll
        for (int nt = 0; nt < 8; nt++) {
            int col = warpN * 64 + nt * 8 + tg * 2;
            if (r0 < N_NODES) {
                float2 v = make_float2(acc[mt][nt][0] * d0, acc[mt][nt][1] * d0);
                *reinterpret_cast<float2*>(P + (size_t)r0 * HIDDEN + col) = v;
            }
            if (r1 < N_NODES) {
                float2 v = make_float2(acc[mt][nt][2] * d1, acc[mt][nt][3] * d1);
                *reinterpret_cast<float2*>(P + (size_t)r1 * HIDDEN + col) = v;
            }
        }
    }
}

// ---------------- SIMT tiled SGEMM (layer 2), dinv row-scale epilogue ----------------
template <int BM, int BN, int BK, int TM, int TN>
__global__ void gemm_scaled_kernel(const float* __restrict__ A,
                                   const float* __restrict__ B,
                                   float* __restrict__ P,
                                   int M, int N, int K) {
    constexpr int NT = (BM / TM) * (BN / TN);
    __shared__ float As[BK][BM + 4];
    __shared__ float Bs[BK][BN];

    const int tid  = threadIdx.x;
    const int tCol = tid % (BN / TN);
    const int tRow = tid / (BN / TN);
    const int rowBase = blockIdx.x * BM;

    float acc[TM][TN];
#pragma unroll
    for (int i = 0; i < TM; i++)
#pragma unroll
        for (int j = 0; j < TN; j++) acc[i][j] = 0.0f;

    for (int k0 = 0; k0 < K; k0 += BK) {
#pragma unroll
        for (int i = tid; i < BM * BK / 4; i += NT) {
            int r  = i / (BK / 4);
            int cc = (i % (BK / 4)) * 4;
            int gr = rowBase + r;
            float4 v = make_float4(0.f, 0.f, 0.f, 0.f);
            if (gr < M)
                v = *reinterpret_cast<const float4*>(A + (size_t)gr * K + k0 + cc);
            As[cc + 0][r] = v.x;
            As[cc + 1][r] = v.y;
            As[cc + 2][r] = v.z;
            As[cc + 3][r] = v.w;
        }
#pragma unroll
        for (int i = tid; i < BK * BN / 4; i += NT) {
            int r  = i / (BN / 4);
            int cc = (i % (BN / 4)) * 4;
            float4 v = make_float4(0.f, 0.f, 0.f, 0.f);
            if (cc + 3 < N) {
                v = *reinterpret_cast<const float4*>(B + (size_t)(k0 + r) * N + cc);
            } else {
                if (cc + 0 < N) v.x = B[(size_t)(k0 + r) * N + cc + 0];
                if (cc + 1 < N) v.y = B[(size_t)(k0 + r) * N + cc + 1];
                if (cc + 2 < N) v.z = B[(size_t)(k0 + r) * N + cc + 2];
            }
            Bs[r][cc + 0] = v.x;
            Bs[r][cc + 1] = v.y;
            Bs[r][cc + 2] = v.z;
            Bs[r][cc + 3] = v.w;
        }
        __syncthreads();

#pragma unroll
        for (int k = 0; k < BK; k++) {
            float rm[TM], rn[TN];
#pragma unroll
            for (int i = 0; i < TM; i++) rm[i] = As[k][tRow * TM + i];
#pragma unroll
            for (int j = 0; j < TN; j++) rn[j] = Bs[k][tCol * TN + j];
#pragma unroll
            for (int i = 0; i < TM; i++)
#pragma unroll
                for (int j = 0; j < TN; j++) acc[i][j] += rm[i] * rn[j];
        }
        __syncthreads();
    }

#pragma unroll
    for (int i = 0; i < TM; i++) {
        int row = rowBase + tRow * TM + i;
        if (row >= M) continue;
        float s = g_dinv[row];
#pragma unroll
        for (int j = 0; j < TN; j++) {
            int col = tCol * TN + j;
            if (col < N)
                P[(size_t)row * N + col] = acc[i][j] * s;
        }
    }
}

// ---------------- layer-1 aggregation (warp per node, 128 cols) ----------------
__global__ void agg1_kernel(const float* __restrict__ b1) {
    int t = blockIdx.x * blockDim.x + threadIdx.x;
    int n = t >> 5;
    int c = t & 31;
    if (n >= N_NODES) return;

    int beg = g_rowptr[n];
    int end = g_rowptr[n + 1];
    float4 acc = *reinterpret_cast<const float4*>(g_P1 + (size_t)n * HIDDEN + c * 4);
    for (int e = beg; e < end; e++) {
        int s = g_cidx[e];
        float4 v = *reinterpret_cast<const float4*>(g_P1 + (size_t)s * HIDDEN + c * 4);
        acc.x += v.x; acc.y += v.y; acc.z += v.z; acc.w += v.w;
    }
    float sc = g_dinv[n];
    float4 bb = *reinterpret_cast<const float4*>(b1 + c * 4);
    float4 o;
    o.x = fmaxf(fmaf(acc.x, sc, bb.x), 0.0f);
    o.y = fmaxf(fmaf(acc.y, sc, bb.y), 0.0f);
    o.z = fmaxf(fmaf(acc.z, sc, bb.z), 0.0f);
    o.w = fmaxf(fmaf(acc.w, sc, bb.w), 0.0f);
    *reinterpret_cast<float4*>(g_X1 + (size_t)n * HIDDEN + c * 4) = o;
}

// ---------------- layer-2 aggregation (10 float4 chunks per node) ----------------
__global__ void agg2_kernel(const float* __restrict__ b2, float* __restrict__ out) {
    int t = blockIdx.x * blockDim.x + threadIdx.x;
    int n = t / 10;
    int c = t % 10;
    if (n >= N_NODES) return;

    int beg = g_rowptr[n];
    int end = g_rowptr[n + 1];
    float4 acc = *reinterpret_cast<const float4*>(g_P2 + (size_t)n * N_CLASSES + c * 4);
    for (int e = beg; e < end; e++) {
        int s = g_cidx[e];
        float4 v = *reinterpret_cast<const float4*>(g_P2 + (size_t)s * N_CLASSES + c * 4);
        acc.x += v.x; acc.y += v.y; acc.z += v.z; acc.w += v.w;
    }
    float sc = g_dinv[n];
    float4 bb = *reinterpret_cast<const float4*>(b2 + c * 4);
    float4 o;
    o.x = fmaf(acc.x, sc, bb.x);
    o.y = fmaf(acc.y, sc, bb.y);
    o.z = fmaf(acc.z, sc, bb.z);
    o.w = fmaf(acc.w, sc, bb.w);
    *reinterpret_cast<float4*>(out + (size_t)n * N_CLASSES + c * 4) = o;
}

// ---------------- launch ----------------
extern "C" void kernel_launch(void* const* d_in, const int* in_sizes, int n_in,
                              void* d_out, int out_size) {
    const float* x  = (const float*)d_in[0];
    const int*   ei = (const int*)d_in[1];     // int32 (JAX x64 disabled)
    const float* W1 = (const float*)d_in[2];
    const float* b1 = (const float*)d_in[3];
    const float* W2 = (const float*)d_in[4];
    const float* b2 = (const float*)d_in[5];
    float* out = (float*)d_out;

    float *p1, *x1, *p2;
    cudaGetSymbolAddress((void**)&p1, g_P1);
    cudaGetSymbolAddress((void**)&x1, g_X1);
    cudaGetSymbolAddress((void**)&p2, g_P2);

    const int T = 256;

    // CSR build + dinv
    zero_cnt_kernel<<<(N_NODES + T - 1) / T, T>>>();
    hist_kernel<<<(N_EDGES + T - 1) / T, T>>>(ei);
    scan1_kernel<<<NBLK, SCAN_B>>>();
    scan2_kernel<<<1, 32>>>();
    scan3_kernel<<<(N_NODES + T - 1) / T, T>>>();
    place_kernel<<<(N_EDGES + T - 1) / T, T>>>(ei);

    // W1 split (hi/lo bf16, transposed)
    wsplit_kernel<<<(HIDDEN * IN_DIM + T - 1) / T, T>>>(W1);

    // layer 1: warp-MMA split-bf16 GEMM
    gemm1_mma_kernel<<<(N_NODES + 127) / 128, 256>>>(x, p1);
    agg1_kernel<<<(N_NODES * 32 + T - 1) / T, T>>>(b1);

    // layer 2
    gemm_scaled_kernel<128, 64, 16, 8, 8>
        <<<(N_NODES + 127) / 128, 128>>>(x1, W2, p2, N_NODES, N_CLASSES, HIDDEN);
    agg2_kernel<<<(N_NODES * 10 + T - 1) / T, T>>>(b2, out);
}

// round 8
// speedup vs baseline: 1.7001x; 1.2037x over previous
#include <cuda_runtime.h>
#include <cuda_bf16.h>
#include <cstdint>
#include <cstddef>

#define N_NODES   100000
#define N_EDGES   1600000
#define IN_DIM    256
#define HIDDEN    128
#define N_CLASSES 40

#define SCAN_B 1024
#define NBLK   ((N_NODES + SCAN_B - 1) / SCAN_B)   // 98

// ---------------- static device scratch (no allocations allowed) ----------------
__device__ __align__(16) float g_dinv[N_NODES];
__device__ int  g_cnt[N_NODES];
__device__ int  g_rowptr[N_NODES + 1];
__device__ int  g_cursor[N_NODES];
__device__ int  g_bsum[NBLK];
__device__ int  g_cidx[N_EDGES];
__device__ __align__(16) float g_P1[(size_t)N_NODES * HIDDEN];
__device__ __align__(16) float g_X1[(size_t)N_NODES * HIDDEN];
__device__ __align__(16) float g_P2[(size_t)N_NODES * N_CLASSES];
// W1 transposed to [n][k], fp32 values pre-rounded to tf32
__device__ __align__(16) float g_Wt[HIDDEN * IN_DIM];

// ---------------- CSR build ----------------
__global__ void hist_kernel(const int* __restrict__ ei) {
    int e = blockIdx.x * blockDim.x + threadIdx.x;
    if (e < N_EDGES) atomicAdd(&g_cnt[ei[N_EDGES + e]], 1);
}

__global__ void scan1_kernel() {
    __shared__ int sh[SCAN_B];
    int tid = threadIdx.x;
    int i = blockIdx.x * SCAN_B + tid;
    int v = (i < N_NODES) ? g_cnt[i] : 0;
    sh[tid] = v;
    __syncthreads();
#pragma unroll
    for (int off = 1; off < SCAN_B; off <<= 1) {
        int t = (tid >= off) ? sh[tid - off] : 0;
        __syncthreads();
        sh[tid] += t;
        __syncthreads();
    }
    if (i < N_NODES) g_rowptr[i] = sh[tid] - v;
    if (tid == SCAN_B - 1) g_bsum[blockIdx.x] = sh[tid];
}

// parallel exclusive scan of the 98 block sums (one block of 128 threads)
__global__ void scan2_kernel() {
    __shared__ int wsum[4];
    int t = threadIdx.x;
    int v = (t < NBLK) ? g_bsum[t] : 0;
    int x = v;
#pragma unroll
    for (int off = 1; off < 32; off <<= 1) {
        int y = __shfl_up_sync(0xFFFFFFFFu, x, off);
        if ((t & 31) >= off) x += y;
    }
    if ((t & 31) == 31) wsum[t >> 5] = x;
    __syncthreads();
    int add = 0;
#pragma unroll
    for (int w = 0; w < 4; w++)
        if (w < (t >> 5)) add += wsum[w];
    if (t < NBLK) g_bsum[t] = x - v + add;   // exclusive
}

__global__ void scan3_kernel() {
    int i = blockIdx.x * blockDim.x + threadIdx.x;
    if (i < N_NODES) {
        int r = g_rowptr[i] + g_bsum[i / SCAN_B];
        g_rowptr[i] = r;
        g_cursor[i] = r;
        g_dinv[i] = rsqrtf((float)g_cnt[i] + 1.0f);
    }
    if (i == 0) g_rowptr[N_NODES] = N_EDGES;
}

__global__ void place_kernel(const int* __restrict__ ei) {
    int e = blockIdx.x * blockDim.x + threadIdx.x;
    if (e < N_EDGES) {
        int s = ei[e];
        int d = ei[N_EDGES + e];
        int pos = atomicAdd(&g_cursor[d], 1);
        g_cidx[pos] = s;
    }
}

// ---------------- W1 transpose + tf32 round (once per launch, tiny) ----------------
__device__ __forceinline__ float to_tf32(float f) {
    uint32_t r;
    asm("cvt.rna.tf32.f32 %0, %1;" : "=r"(r) : "f"(f));
    return __uint_as_float(r);
}

__global__ void wt_kernel(const float* __restrict__ W1) {
    int i = blockIdx.x * blockDim.x + threadIdx.x;   // over HIDDEN*IN_DIM, n-major
    if (i >= HIDDEN * IN_DIM) return;
    int n = i / IN_DIM;
    int k = i % IN_DIM;
    g_Wt[i] = to_tf32(W1[(size_t)k * HIDDEN + n]);
}

// ================= warp-MMA tf32 GEMM for layer 1 =================
// P1[m][n] = dinv[m]*sum_k x[m][k]*W1[k][n], single-pass tf32.
#define PITCHF 36   // floats per smem row (32 data + 4 pad); 144B, 16B-aligned

__device__ __forceinline__ void mma_tf32(float c[4], uint32_t a0, uint32_t a1, uint32_t a2,
                                         uint32_t a3, uint32_t b0, uint32_t b1) {
    asm volatile(
        "mma.sync.aligned.m16n8k8.row.col.f32.tf32.tf32.f32 "
        "{%0,%1,%2,%3}, {%4,%5,%6,%7}, {%8,%9}, {%0,%1,%2,%3};"
        : "+f"(c[0]), "+f"(c[1]), "+f"(c[2]), "+f"(c[3])
        : "r"(a0), "r"(a1), "r"(a2), "r"(a3), "r"(b0), "r"(b1));
}

__global__ void __launch_bounds__(256) gemm1_mma_kernel(const float* __restrict__ X,
                                                        float* __restrict__ P) {
    __shared__ __align__(16) float As[128 * PITCHF];
    __shared__ __align__(16) float Bs[128 * PITCHF];

    const int tid = threadIdx.x, lane = tid & 31, wid = tid >> 5;
    const int warpM = wid & 3;      // 4 warps over M (32 rows each)
    const int warpN = wid >> 2;     // 2 warps over N (64 cols each)
    const int rowBase = blockIdx.x * 128;
    const int gq = lane >> 2;       // groupID 0..7
    const int tg = lane & 3;        // thread-in-group 0..3

    float acc[2][8][4];
#pragma unroll
    for (int m = 0; m < 2; m++)
#pragma unroll
        for (int n = 0; n < 8; n++)
#pragma unroll
            for (int r = 0; r < 4; r++) acc[m][n][r] = 0.0f;

    for (int k0 = 0; k0 < IN_DIM; k0 += 32) {
        // ---- stage A: 128 rows x 32 k fp32 -> tf32-rounded into smem ----
#pragma unroll
        for (int i = tid; i < 1024; i += 256) {
            int r  = i >> 3;
            int c4 = (i & 7) * 4;
            int gr = rowBase + r;
            float4 v = (gr < N_NODES)
                ? *reinterpret_cast<const float4*>(X + (size_t)gr * IN_DIM + k0 + c4)
                : make_float4(0.f, 0.f, 0.f, 0.f);
            v.x = to_tf32(v.x); v.y = to_tf32(v.y);
            v.z = to_tf32(v.z); v.w = to_tf32(v.w);
            *reinterpret_cast<float4*>(As + r * PITCHF + c4) = v;
        }
        // ---- stage B: pure float4 copy of pre-rounded Wt chunk [128 n][32 k] ----
#pragma unroll
        for (int i = tid; i < 1024; i += 256) {
            int n  = i >> 3;
            int c4 = (i & 7) * 4;
            *reinterpret_cast<float4*>(Bs + n * PITCHF + c4) =
                *reinterpret_cast<const float4*>(g_Wt + (size_t)n * IN_DIM + k0 + c4);
        }
        __syncthreads();

#pragma unroll
        for (int kk = 0; kk < 32; kk += 8) {
            uint32_t bf[8][2];
#pragma unroll
            for (int nt = 0; nt < 8; nt++) {
                int n = warpN * 64 + nt * 8 + gq;
                const uint32_t* bp = reinterpret_cast<const uint32_t*>(Bs + n * PITCHF + kk + tg);
                bf[nt][0] = bp[0];
                bf[nt][1] = bp[4];
            }
#pragma unroll
            for (int mt = 0; mt < 2; mt++) {
                int r0 = warpM * 32 + mt * 16 + gq;
                const uint32_t* a0p = reinterpret_cast<const uint32_t*>(As + r0 * PITCHF + kk + tg);
                const uint32_t* a8p = reinterpret_cast<const uint32_t*>(As + (r0 + 8) * PITCHF + kk + tg);
                uint32_t a0 = a0p[0], a1 = a8p[0], a2 = a0p[4], a3 = a8p[4];
#pragma unroll
                for (int nt = 0; nt < 8; nt++)
                    mma_tf32(acc[mt][nt], a0, a1, a2, a3, bf[nt][0], bf[nt][1]);
            }
        }
        __syncthreads();
    }

    // ---- epilogue: scale by dinv[row], write P1 ----
#pragma unroll
    for (int mt = 0; mt < 2; mt++) {
        int r0 = rowBase + warpM * 32 + mt * 16 + gq;
        int r1 = r0 + 8;
        float d0 = (r0 < N_NODES) ? g_dinv[r0] : 0.f;
        float d1 = (r1 < N_NODES) ? g_dinv[r1] : 0.f;
#pragma unroll
        for (int nt = 0; nt < 8; nt++) {
            int col = warpN * 64 + nt * 8 + tg * 2;
            if (r0 < N_NODES) {
                float2 v = make_float2(acc[mt][nt][0] * d0, acc[mt][nt][1] * d0);
                *reinterpret_cast<float2*>(P + (size_t)r0 * HIDDEN + col) = v;
            }
            if (r1 < N_NODES) {
                float2 v = make_float2(acc[mt][nt][2] * d1, acc[mt][nt][3] * d1);
                *reinterpret_cast<float2*>(P + (size_t)r1 * HIDDEN + col) = v;
            }
        }
    }
}

// ---------------- SIMT tiled SGEMM (layer 2), dinv row-scale epilogue ----------------
template <int BM, int BN, int BK, int TM, int TN>
__global__ void gemm_scaled_kernel(const float* __restrict__ A,
                                   const float* __restrict__ B,
                                   float* __restrict__ P,
                                   int M, int N, int K) {
    constexpr int NT = (BM / TM) * (BN / TN);
    __shared__ float As[BK][BM + 4];
    __shared__ float Bs[BK][BN];

    const int tid  = threadIdx.x;
    const int tCol = tid % (BN / TN);
    const int tRow = tid / (BN / TN);
    const int rowBase = blockIdx.x * BM;

    float acc[TM][TN];
#pragma unroll
    for (int i = 0; i < TM; i++)
#pragma unroll
        for (int j = 0; j < TN; j++) acc[i][j] = 0.0f;

    for (int k0 = 0; k0 < K; k0 += BK) {
#pragma unroll
        for (int i = tid; i < BM * BK / 4; i += NT) {
            int r  = i / (BK / 4);
            int cc = (i % (BK / 4)) * 4;
            int gr = rowBase + r;
            float4 v = make_float4(0.f, 0.f, 0.f, 0.f);
            if (gr < M)
                v = *reinterpret_cast<const float4*>(A + (size_t)gr * K + k0 + cc);
            As[cc + 0][r] = v.x;
            As[cc + 1][r] = v.y;
            As[cc + 2][r] = v.z;
            As[cc + 3][r] = v.w;
        }
#pragma unroll
        for (int i = tid; i < BK * BN / 4; i += NT) {
            int r  = i / (BN / 4);
            int cc = (i % (BN / 4)) * 4;
            float4 v = make_float4(0.f, 0.f, 0.f, 0.f);
            if (cc + 3 < N) {
                v = *reinterpret_cast<const float4*>(B + (size_t)(k0 + r) * N + cc);
            } else {
                if (cc + 0 < N) v.x = B[(size_t)(k0 + r) * N + cc + 0];
                if (cc + 1 < N) v.y = B[(size_t)(k0 + r) * N + cc + 1];
                if (cc + 2 < N) v.z = B[(size_t)(k0 + r) * N + cc + 2];
            }
            Bs[r][cc + 0] = v.x;
            Bs[r][cc + 1] = v.y;
            Bs[r][cc + 2] = v.z;
            Bs[r][cc + 3] = v.w;
        }
        __syncthreads();

#pragma unroll
        for (int k = 0; k < BK; k++) {
            float rm[TM], rn[TN];
#pragma unroll
            for (int i = 0; i < TM; i++) rm[i] = As[k][tRow * TM + i];
#pragma unroll
            for (int j = 0; j < TN; j++) rn[j] = Bs[k][tCol * TN + j];
#pragma unroll
            for (int i = 0; i < TM; i++)
#pragma unroll
                for (int j = 0; j < TN; j++) acc[i][j] += rm[i] * rn[j];
        }
        __syncthreads();
    }

#pragma unroll
    for (int i = 0; i < TM; i++) {
        int row = rowBase + tRow * TM + i;
        if (row >= M) continue;
        float s = g_dinv[row];
#pragma unroll
        for (int j = 0; j < TN; j++) {
            int col = tCol * TN + j;
            if (col < N)
                P[(size_t)row * N + col] = acc[i][j] * s;
        }
    }
}

// ---------------- layer-1 aggregation (warp per node, 128 cols) ----------------
__global__ void agg1_kernel(const float* __restrict__ b1) {
    int t = blockIdx.x * blockDim.x + threadIdx.x;
    int n = t >> 5;
    int c = t & 31;
    if (n >= N_NODES) return;

    int beg = g_rowptr[n];
    int end = g_rowptr[n + 1];
    float4 acc = *reinterpret_cast<const float4*>(g_P1 + (size_t)n * HIDDEN + c * 4);
    for (int e = beg; e < end; e++) {
        int s = g_cidx[e];
        float4 v = *reinterpret_cast<const float4*>(g_P1 + (size_t)s * HIDDEN + c * 4);
        acc.x += v.x; acc.y += v.y; acc.z += v.z; acc.w += v.w;
    }
    float sc = g_dinv[n];
    float4 bb = *reinterpret_cast<const float4*>(b1 + c * 4);
    float4 o;
    o.x = fmaxf(fmaf(acc.x, sc, bb.x), 0.0f);
    o.y = fmaxf(fmaf(acc.y, sc, bb.y), 0.0f);
    o.z = fmaxf(fmaf(acc.z, sc, bb.z), 0.0f);
    o.w = fmaxf(fmaf(acc.w, sc, bb.w), 0.0f);
    *reinterpret_cast<float4*>(g_X1 + (size_t)n * HIDDEN + c * 4) = o;
}

// ---------------- layer-2 aggregation (10 float4 chunks per node) ----------------
__global__ void agg2_kernel(const float* __restrict__ b2, float* __restrict__ out) {
    int t = blockIdx.x * blockDim.x + threadIdx.x;
    int n = t / 10;
    int c = t % 10;
    if (n >= N_NODES) return;

    int beg = g_rowptr[n];
    int end = g_rowptr[n + 1];
    float4 acc = *reinterpret_cast<const float4*>(g_P2 + (size_t)n * N_CLASSES + c * 4);
    for (int e = beg; e < end; e++) {
        int s = g_cidx[e];
        float4 v = *reinterpret_cast<const float4*>(g_P2 + (size_t)s * N_CLASSES + c * 4);
        acc.x += v.x; acc.y += v.y; acc.z += v.z; acc.w += v.w;
    }
    float sc = g_dinv[n];
    float4 bb = *reinterpret_cast<const float4*>(b2 + c * 4);
    float4 o;
    o.x = fmaf(acc.x, sc, bb.x);
    o.y = fmaf(acc.y, sc, bb.y);
    o.z = fmaf(acc.z, sc, bb.z);
    o.w = fmaf(acc.w, sc, bb.w);
    *reinterpret_cast<float4*>(out + (size_t)n * N_CLASSES + c * 4) = o;
}

// ---------------- launch ----------------
extern "C" void kernel_launch(void* const* d_in, const int* in_sizes, int n_in,
                              void* d_out, int out_size) {
    const float* x  = (const float*)d_in[0];
    const int*   ei = (const int*)d_in[1];     // int32 (JAX x64 disabled)
    const float* W1 = (const float*)d_in[2];
    const float* b1 = (const float*)d_in[3];
    const float* W2 = (const float*)d_in[4];
    const float* b2 = (const float*)d_in[5];
    float* out = (float*)d_out;

    float *p1, *x1, *p2;
    int* cnt;
    cudaGetSymbolAddress((void**)&p1, g_P1);
    cudaGetSymbolAddress((void**)&x1, g_X1);
    cudaGetSymbolAddress((void**)&p2, g_P2);
    cudaGetSymbolAddress((void**)&cnt, g_cnt);

    const int T = 256;

    // CSR build + dinv
    cudaMemsetAsync(cnt, 0, N_NODES * sizeof(int));
    hist_kernel<<<(N_EDGES + T - 1) / T, T>>>(ei);
    scan1_kernel<<<NBLK, SCAN_B>>>();
    scan2_kernel<<<1, 128>>>();
    scan3_kernel<<<(N_NODES + T - 1) / T, T>>>();
    place_kernel<<<(N_EDGES + T - 1) / T, T>>>(ei);

    // W1 transpose + tf32 round
    wt_kernel<<<(HIDDEN * IN_DIM + T - 1) / T, T>>>(W1);

    // layer 1: warp-MMA tf32 GEMM
    gemm1_mma_kernel<<<(N_NODES + 127) / 128, 256>>>(x, p1);
    agg1_kernel<<<(N_NODES * 32 + T - 1) / T, T>>>(b1);

    // layer 2
    gemm_scaled_kernel<128, 64, 16, 8, 8>
        <<<(N_NODES + 127) / 128, 128>>>(x1, W2, p2, N_NODES, N_CLASSES, HIDDEN);
    agg2_kernel<<<(N_NODES * 10 + T - 1) / T, T>>>(b2, out);
}

// round 9
// speedup vs baseline: 2.0141x; 1.1847x over previous
#include <cuda_runtime.h>
#include <cuda_bf16.h>
#include <cstdint>
#include <cstddef>

#define N_NODES   100000
#define N_EDGES   1600000
#define IN_DIM    256
#define HIDDEN    128
#define N_CLASSES 40

#define SCAN_B 1024
#define NBLK   ((N_NODES + SCAN_B - 1) / SCAN_B)   // 98

// ---------------- static device scratch (no allocations allowed) ----------------
__device__ __align__(16) float g_dinv[N_NODES];
__device__ int  g_cnt[N_NODES];
__device__ int  g_rowptr[N_NODES + 1];
__device__ int  g_cursor[N_NODES];
__device__ int  g_bsum[NBLK];
__device__ int  g_cidx[N_EDGES];
__device__ __align__(16) float g_P1[(size_t)N_NODES * HIDDEN];
__device__ __align__(16) float g_X1[(size_t)N_NODES * HIDDEN];
__device__ __align__(16) float g_P2[(size_t)N_NODES * N_CLASSES];
// W1 transposed to [n][k], tf32-rounded, k-permuted (pairs (t,t+4)->(2t,2t+1) per 8-block)
__device__ __align__(16) float g_Wt[HIDDEN * IN_DIM];
// W2 transposed to [n][k] (40 x 128), tf32-rounded, k-permuted
__device__ __align__(16) float g_W2t[N_CLASSES * HIDDEN];

// k-dim permutation within 8-blocks: frag pair (t, t+4) becomes adjacent (2t, 2t+1)
__device__ __forceinline__ int kperm(int k) {
    int t = k & 7;
    return (k & ~7) | ((t < 4) ? (t << 1) : (((t - 4) << 1) | 1));
}

// ---------------- CSR build ----------------
__global__ void hist_kernel(const int* __restrict__ ei) {
    int e = blockIdx.x * blockDim.x + threadIdx.x;
    if (e < N_EDGES) atomicAdd(&g_cnt[ei[N_EDGES + e]], 1);
}

__global__ void scan1_kernel() {
    __shared__ int sh[SCAN_B];
    int tid = threadIdx.x;
    int i = blockIdx.x * SCAN_B + tid;
    int v = (i < N_NODES) ? g_cnt[i] : 0;
    sh[tid] = v;
    __syncthreads();
#pragma unroll
    for (int off = 1; off < SCAN_B; off <<= 1) {
        int t = (tid >= off) ? sh[tid - off] : 0;
        __syncthreads();
        sh[tid] += t;
        __syncthreads();
    }
    if (i < N_NODES) g_rowptr[i] = sh[tid] - v;
    if (tid == SCAN_B - 1) g_bsum[blockIdx.x] = sh[tid];
}

__global__ void scan2_kernel() {
    __shared__ int wsum[4];
    int t = threadIdx.x;
    int v = (t < NBLK) ? g_bsum[t] : 0;
    int x = v;
#pragma unroll
    for (int off = 1; off < 32; off <<= 1) {
        int y = __shfl_up_sync(0xFFFFFFFFu, x, off);
        if ((t & 31) >= off) x += y;
    }
    if ((t & 31) == 31) wsum[t >> 5] = x;
    __syncthreads();
    int add = 0;
#pragma unroll
    for (int w = 0; w < 4; w++)
        if (w < (t >> 5)) add += wsum[w];
    if (t < NBLK) g_bsum[t] = x - v + add;
}

__global__ void scan3_kernel() {
    int i = blockIdx.x * blockDim.x + threadIdx.x;
    if (i < N_NODES) {
        int r = g_rowptr[i] + g_bsum[i / SCAN_B];
        g_rowptr[i] = r;
        g_cursor[i] = r;
        g_dinv[i] = rsqrtf((float)g_cnt[i] + 1.0f);
    }
    if (i == 0) g_rowptr[N_NODES] = N_EDGES;
}

__global__ void place_kernel(const int* __restrict__ ei) {
    int e = blockIdx.x * blockDim.x + threadIdx.x;
    if (e < N_EDGES) {
        int s = ei[e];
        int d = ei[N_EDGES + e];
        int pos = atomicAdd(&g_cursor[d], 1);
        g_cidx[pos] = s;
    }
}

// ---------------- weight prep (once per launch, tiny) ----------------
__device__ __forceinline__ float to_tf32(float f) {
    uint32_t r;
    asm("cvt.rna.tf32.f32 %0, %1;" : "=r"(r) : "f"(f));
    return __uint_as_float(r);
}

__global__ void wt_kernel(const float* __restrict__ W1) {
    int i = blockIdx.x * blockDim.x + threadIdx.x;
    if (i >= HIDDEN * IN_DIM) return;
    int n = i / IN_DIM;
    int k = i % IN_DIM;
    g_Wt[n * IN_DIM + kperm(k)] = to_tf32(W1[(size_t)k * HIDDEN + n]);
}

__global__ void w2t_kernel(const float* __restrict__ W2) {
    int i = blockIdx.x * blockDim.x + threadIdx.x;
    if (i >= N_CLASSES * HIDDEN) return;
    int n = i / HIDDEN;
    int k = i % HIDDEN;
    g_W2t[n * HIDDEN + kperm(k)] = to_tf32(W2[(size_t)k * N_CLASSES + n]);
}

// ---------------- tf32 mma helper ----------------
__device__ __forceinline__ void mma_tf32(float c[4], uint32_t a0, uint32_t a1, uint32_t a2,
                                         uint32_t a3, uint32_t b0, uint32_t b1) {
    asm volatile(
        "mma.sync.aligned.m16n8k8.row.col.f32.tf32.tf32.f32 "
        "{%0,%1,%2,%3}, {%4,%5,%6,%7}, {%8,%9}, {%0,%1,%2,%3};"
        : "+f"(c[0]), "+f"(c[1]), "+f"(c[2]), "+f"(c[3])
        : "r"(a0), "r"(a1), "r"(a2), "r"(a3), "r"(b0), "r"(b1));
}

// ================= layer-1 tf32 GEMM: P1 = dinv ⊙ (X @ W1) =================
#define PITCHF 36   // floats per smem row (32 data + 4 pad)

__global__ void __launch_bounds__(256) gemm1_mma_kernel(const float* __restrict__ X,
                                                        float* __restrict__ P) {
    __shared__ __align__(16) float As[128 * PITCHF];
    __shared__ __align__(16) float Bs[128 * PITCHF];   // k-permuted

    const int tid = threadIdx.x, lane = tid & 31, wid = tid >> 5;
    const int warpM = wid & 3;
    const int warpN = wid >> 2;
    const int rowBase = blockIdx.x * 128;
    const int gq = lane >> 2;
    const int tg = lane & 3;

    float acc[2][8][4];
#pragma unroll
    for (int m = 0; m < 2; m++)
#pragma unroll
        for (int n = 0; n < 8; n++)
#pragma unroll
            for (int r = 0; r < 4; r++) acc[m][n][r] = 0.0f;

    for (int k0 = 0; k0 < IN_DIM; k0 += 32) {
        // stage A (logical k order): tf32-round
#pragma unroll
        for (int i = tid; i < 1024; i += 256) {
            int r  = i >> 3;
            int c4 = (i & 7) * 4;
            int gr = rowBase + r;
            float4 v = (gr < N_NODES)
                ? *reinterpret_cast<const float4*>(X + (size_t)gr * IN_DIM + k0 + c4)
                : make_float4(0.f, 0.f, 0.f, 0.f);
            v.x = to_tf32(v.x); v.y = to_tf32(v.y);
            v.z = to_tf32(v.z); v.w = to_tf32(v.w);
            *reinterpret_cast<float4*>(As + r * PITCHF + c4) = v;
        }
        // stage B: pure float4 copy (g_Wt already tf32 + permuted)
#pragma unroll
        for (int i = tid; i < 1024; i += 256) {
            int n  = i >> 3;
            int c4 = (i & 7) * 4;
            *reinterpret_cast<float4*>(Bs + n * PITCHF + c4) =
                *reinterpret_cast<const float4*>(g_Wt + (size_t)n * IN_DIM + k0 + c4);
        }
        __syncthreads();

#pragma unroll
        for (int kk = 0; kk < 32; kk += 8) {
            uint32_t bf[8][2];
#pragma unroll
            for (int nt = 0; nt < 8; nt++) {
                int n = warpN * 64 + nt * 8 + gq;
                uint2 bb = *reinterpret_cast<const uint2*>(Bs + n * PITCHF + kk + 2 * tg);
                bf[nt][0] = bb.x;
                bf[nt][1] = bb.y;
            }
#pragma unroll
            for (int mt = 0; mt < 2; mt++) {
                int r0 = warpM * 32 + mt * 16 + gq;
                const uint32_t* a0p = reinterpret_cast<const uint32_t*>(As + r0 * PITCHF + kk + tg);
                const uint32_t* a8p = reinterpret_cast<const uint32_t*>(As + (r0 + 8) * PITCHF + kk + tg);
                uint32_t a0 = a0p[0], a1 = a8p[0], a2 = a0p[4], a3 = a8p[4];
#pragma unroll
                for (int nt = 0; nt < 8; nt++)
                    mma_tf32(acc[mt][nt], a0, a1, a2, a3, bf[nt][0], bf[nt][1]);
            }
        }
        __syncthreads();
    }

#pragma unroll
    for (int mt = 0; mt < 2; mt++) {
        int r0 = rowBase + warpM * 32 + mt * 16 + gq;
        int r1 = r0 + 8;
        float d0 = (r0 < N_NODES) ? g_dinv[r0] : 0.f;
        float d1 = (r1 < N_NODES) ? g_dinv[r1] : 0.f;
#pragma unroll
        for (int nt = 0; nt < 8; nt++) {
            int col = warpN * 64 + nt * 8 + tg * 2;
            if (r0 < N_NODES) {
                float2 v = make_float2(acc[mt][nt][0] * d0, acc[mt][nt][1] * d0);
                *reinterpret_cast<float2*>(P + (size_t)r0 * HIDDEN + col) = v;
            }
            if (r1 < N_NODES) {
                float2 v = make_float2(acc[mt][nt][2] * d1, acc[mt][nt][3] * d1);
                *reinterpret_cast<float2*>(P + (size_t)r1 * HIDDEN + col) = v;
            }
        }
    }
}

// ================= layer-2 tf32 GEMM: P2 = dinv ⊙ (X1 @ W2) =================
// CTA: 256 rows x 40 cols; 8 warps over M; B (40x128) fully smem-resident.
#define PITCH2 132  // floats per Bs row (128 data + 4 pad)

__global__ void __launch_bounds__(256) gemm2_mma_kernel(const float* __restrict__ X1,
                                                        float* __restrict__ P) {
    extern __shared__ float dynsm[];
    float* As = dynsm;                       // 256 * PITCHF
    float* Bs = dynsm + 256 * PITCHF;        // 40 * PITCH2

    const int tid = threadIdx.x, lane = tid & 31, wid = tid >> 5;
    const int rowBase = blockIdx.x * 256;
    const int gq = lane >> 2;
    const int tg = lane & 3;

    // load all of W2t (40 x 128) once
    for (int i = tid; i < (N_CLASSES * HIDDEN) / 4; i += 256) {
        int n  = i >> 5;
        int c4 = (i & 31) * 4;
        *reinterpret_cast<float4*>(Bs + n * PITCH2 + c4) =
            *reinterpret_cast<const float4*>(g_W2t + (size_t)n * HIDDEN + c4);
    }

    float acc[2][5][4];
#pragma unroll
    for (int m = 0; m < 2; m++)
#pragma unroll
        for (int n = 0; n < 5; n++)
#pragma unroll
            for (int r = 0; r < 4; r++) acc[m][n][r] = 0.0f;

    for (int k0 = 0; k0 < HIDDEN; k0 += 32) {
        // stage A: pure float4 copy (X1 already tf32-rounded by agg1)
#pragma unroll
        for (int i = tid; i < 2048; i += 256) {
            int r  = i >> 3;
            int c4 = (i & 7) * 4;
            int gr = rowBase + r;
            float4 v = (gr < N_NODES)
                ? *reinterpret_cast<const float4*>(X1 + (size_t)gr * HIDDEN + k0 + c4)
                : make_float4(0.f, 0.f, 0.f, 0.f);
            *reinterpret_cast<float4*>(As + r * PITCHF + c4) = v;
        }
        __syncthreads();

#pragma unroll
        for (int kk = 0; kk < 32; kk += 8) {
            uint32_t bf[5][2];
#pragma unroll
            for (int nt = 0; nt < 5; nt++) {
                int n = nt * 8 + gq;
                uint2 bb = *reinterpret_cast<const uint2*>(Bs + n * PITCH2 + k0 + kk + 2 * tg);
                bf[nt][0] = bb.x;
                bf[nt][1] = bb.y;
            }
#pragma unroll
            for (int mt = 0; mt < 2; mt++) {
                int r0 = wid * 32 + mt * 16 + gq;
                const uint32_t* a0p = reinterpret_cast<const uint32_t*>(As + r0 * PITCHF + kk + tg);
                const uint32_t* a8p = reinterpret_cast<const uint32_t*>(As + (r0 + 8) * PITCHF + kk + tg);
                uint32_t a0 = a0p[0], a1 = a8p[0], a2 = a0p[4], a3 = a8p[4];
#pragma unroll
                for (int nt = 0; nt < 5; nt++)
                    mma_tf32(acc[mt][nt], a0, a1, a2, a3, bf[nt][0], bf[nt][1]);
            }
        }
        __syncthreads();
    }

#pragma unroll
    for (int mt = 0; mt < 2; mt++) {
        int r0 = rowBase + wid * 32 + mt * 16 + gq;
        int r1 = r0 + 8;
        float d0 = (r0 < N_NODES) ? g_dinv[r0] : 0.f;
        float d1 = (r1 < N_NODES) ? g_dinv[r1] : 0.f;
#pragma unroll
        for (int nt = 0; nt < 5; nt++) {
            int col = nt * 8 + tg * 2;
            if (r0 < N_NODES) {
                float2 v = make_float2(acc[mt][nt][0] * d0, acc[mt][nt][1] * d0);
                *reinterpret_cast<float2*>(P + (size_t)r0 * N_CLASSES + col) = v;
            }
            if (r1 < N_NODES) {
                float2 v = make_float2(acc[mt][nt][2] * d1, acc[mt][nt][3] * d1);
                *reinterpret_cast<float2*>(P + (size_t)r1 * N_CLASSES + col) = v;
            }
        }
    }
}

// ---------------- layer-1 aggregation (warp per node, 128 cols) ----------------
__global__ void agg1_kernel(const float* __restrict__ b1) {
    int t = blockIdx.x * blockDim.x + threadIdx.x;
    int n = t >> 5;
    int c = t & 31;
    if (n >= N_NODES) return;

    int beg = g_rowptr[n];
    int end = g_rowptr[n + 1];
    float4 acc = *reinterpret_cast<const float4*>(g_P1 + (size_t)n * HIDDEN + c * 4);
    for (int e = beg; e < end; e++) {
        int s = g_cidx[e];
        float4 v = *reinterpret_cast<const float4*>(g_P1 + (size_t)s * HIDDEN + c * 4);
        acc.x += v.x; acc.y += v.y; acc.z += v.z; acc.w += v.w;
    }
    float sc = g_dinv[n];
    float4 bb = *reinterpret_cast<const float4*>(b1 + c * 4);
    float4 o;
    // relu + tf32-round so gemm2's A stage is a pure copy
    o.x = to_tf32(fmaxf(fmaf(acc.x, sc, bb.x), 0.0f));
    o.y = to_tf32(fmaxf(fmaf(acc.y, sc, bb.y), 0.0f));
    o.z = to_tf32(fmaxf(fmaf(acc.z, sc, bb.z), 0.0f));
    o.w = to_tf32(fmaxf(fmaf(acc.w, sc, bb.w), 0.0f));
    *reinterpret_cast<float4*>(g_X1 + (size_t)n * HIDDEN + c * 4) = o;
}

// ---------------- layer-2 aggregation (10 float4 chunks per node) ----------------
__global__ void agg2_kernel(const float* __restrict__ b2, float* __restrict__ out) {
    int t = blockIdx.x * blockDim.x + threadIdx.x;
    int n = t / 10;
    int c = t % 10;
    if (n >= N_NODES) return;

    int beg = g_rowptr[n];
    int end = g_rowptr[n + 1];
    float4 acc = *reinterpret_cast<const float4*>(g_P2 + (size_t)n * N_CLASSES + c * 4);
    for (int e = beg; e < end; e++) {
        int s = g_cidx[e];
        float4 v = *reinterpret_cast<const float4*>(g_P2 + (size_t)s * N_CLASSES + c * 4);
        acc.x += v.x; acc.y += v.y; acc.z += v.z; acc.w += v.w;
    }
    float sc = g_dinv[n];
    float4 bb = *reinterpret_cast<const float4*>(b2 + c * 4);
    float4 o;
    o.x = fmaf(acc.x, sc, bb.x);
    o.y = fmaf(acc.y, sc, bb.y);
    o.z = fmaf(acc.z, sc, bb.z);
    o.w = fmaf(acc.w, sc, bb.w);
    *reinterpret_cast<float4*>(out + (size_t)n * N_CLASSES + c * 4) = o;
}

// ---------------- launch ----------------
extern "C" void kernel_launch(void* const* d_in, const int* in_sizes, int n_in,
                              void* d_out, int out_size) {
    const float* x  = (const float*)d_in[0];
    const int*   ei = (const int*)d_in[1];     // int32 (JAX x64 disabled)
    const float* W1 = (const float*)d_in[2];
    const float* b1 = (const float*)d_in[3];
    const float* W2 = (const float*)d_in[4];
    const float* b2 = (const float*)d_in[5];
    float* out = (float*)d_out;

    float *p1, *x1, *p2;
    int* cnt;
    cudaGetSymbolAddress((void**)&p1, g_P1);
    cudaGetSymbolAddress((void**)&x1, g_X1);
    cudaGetSymbolAddress((void**)&p2, g_P2);
    cudaGetSymbolAddress((void**)&cnt, g_cnt);

    const int T = 256;
    const int smem2 = (256 * PITCHF + N_CLASSES * PITCH2) * sizeof(float);
    cudaFuncSetAttribute(gemm2_mma_kernel, cudaFuncAttributeMaxDynamicSharedMemorySize, smem2);

    // CSR build + dinv
    cudaMemsetAsync(cnt, 0, N_NODES * sizeof(int));
    hist_kernel<<<(N_EDGES + T - 1) / T, T>>>(ei);
    scan1_kernel<<<NBLK, SCAN_B>>>();
    scan2_kernel<<<1, 128>>>();
    scan3_kernel<<<(N_NODES + T - 1) / T, T>>>();
    place_kernel<<<(N_EDGES + T - 1) / T, T>>>(ei);

    // weight prep
    wt_kernel<<<(HIDDEN * IN_DIM + T - 1) / T, T>>>(W1);
    w2t_kernel<<<(N_CLASSES * HIDDEN + T - 1) / T, T>>>(W2);

    // layer 1
    gemm1_mma_kernel<<<(N_NODES + 127) / 128, 256>>>(x, p1);
    agg1_kernel<<<(N_NODES * 32 + T - 1) / T, T>>>(b1);

    // layer 2
    gemm2_mma_kernel<<<(N_NODES + 255) / 256, 256, smem2>>>(x1, p2);
    agg2_kernel<<<(N_NODES * 10 + T - 1) / T, T>>>(b2, out);
}